// round 2
// baseline (speedup 1.0000x reference)
#include <cuda_runtime.h>
#include <math.h>

#define NN 100000
#define NE 1600000
#define D 128
#define DOUT 64

// ---------------- scratch (static device globals; no allocs) ----------------
__device__ float4 d_x0[NN * 32];      // 51.2 MB, 16B aligned
__device__ float4 d_x1[NN * 32];      // 51.2 MB
__device__ float4 d_y [NN * 32];      // 51.2 MB
__device__ int    d_deg[NN];
__device__ float  d_norm[NN];
__device__ int    d_rowptr[NN + 1];
__device__ int    d_cursor[NN];
__device__ int    d_col[NE];
__device__ float  d_w[NE];
__device__ int    d_bsums[128];
__device__ int    d_is64;

#define SCAN_B 98   // ceil(100000/1024)

// ---------------- edge dtype detect ----------------
// int64 positive values < 2^31 have zero high words at odd int32 indices.
__global__ void detect_kernel(const int* __restrict__ ei32) {
    if (threadIdx.x == 0) {
        int all_zero = 1;
        #pragma unroll
        for (int i = 0; i < 32; i++)
            if (ei32[2 * i + 1] != 0) all_zero = 0;
        d_is64 = all_zero;
    }
}

__device__ __forceinline__ int load_edge(const int* ei32, int row, int e) {
    // row 0 = src, row 1 = dst
    int v;
    if (d_is64) v = ei32[2 * (row * NE + e)];     // int64 layout, low word
    else        v = ei32[row * NE + e];           // int32 layout
    // clamp so bad data can never fault
    return (v < 0) ? 0 : (v >= NN ? NN - 1 : v);
}

// ---------------- CSR build ----------------
__global__ void zero_deg_kernel() {
    int i = blockIdx.x * blockDim.x + threadIdx.x;
    if (i < NN) d_deg[i] = 0;
}

__global__ void hist_kernel(const int* __restrict__ ei32) {
    int e = blockIdx.x * blockDim.x + threadIdx.x;
    if (e < NE) {
        int dst = load_edge(ei32, 1, e);
        atomicAdd(&d_deg[dst], 1);
    }
}

__global__ void norm_kernel() {
    int i = blockIdx.x * blockDim.x + threadIdx.x;
    if (i < NN) {
        float dg = (float)d_deg[i];
        d_norm[i] = rsqrtf(fmaxf(dg, 1.0f));
    }
}

__global__ void scan1_kernel() {
    __shared__ int s[1024];
    int tid = threadIdx.x;
    int idx = blockIdx.x * 1024 + tid;
    int c = (idx < NN) ? d_deg[idx] : 0;
    s[tid] = c;
    __syncthreads();
    #pragma unroll
    for (int off = 1; off < 1024; off <<= 1) {
        int v = (tid >= off) ? s[tid - off] : 0;
        __syncthreads();
        s[tid] += v;
        __syncthreads();
    }
    if (idx < NN) d_rowptr[idx] = s[tid] - c;   // exclusive within block
    if (tid == 1023) d_bsums[blockIdx.x] = s[1023];
}

__global__ void scan2_kernel() {
    if (threadIdx.x == 0 && blockIdx.x == 0) {
        int run = 0;
        for (int i = 0; i < SCAN_B; i++) {
            int t = d_bsums[i];
            d_bsums[i] = run;
            run += t;
        }
    }
}

__global__ void scan3_kernel() {
    int i = blockIdx.x * blockDim.x + threadIdx.x;
    if (i < NN) {
        int r = d_rowptr[i] + d_bsums[i >> 10];
        d_rowptr[i] = r;
        d_cursor[i] = r;
    }
    if (i == 0) d_rowptr[NN] = NE;
}

__global__ void fill_kernel(const int* __restrict__ ei32) {
    int e = blockIdx.x * blockDim.x + threadIdx.x;
    if (e < NE) {
        int src = load_edge(ei32, 0, e);
        int dst = load_edge(ei32, 1, e);
        int pos = atomicAdd(&d_cursor[dst], 1);
        if (pos < NE) {
            d_col[pos] = src;
            d_w[pos] = d_norm[src] * d_norm[dst];
        }
    }
}

// ---------------- init: x0 = feats*0.5 ; y = x0 ----------------
__global__ void init_kernel(const float* __restrict__ feats) {
    int i = blockIdx.x * blockDim.x + threadIdx.x;   // float4 index, NN*32 total
    if (i < NN * 32) {
        float4 v;
        v.x = 0.5f * feats[i * 4 + 0];
        v.y = 0.5f * feats[i * 4 + 1];
        v.z = 0.5f * feats[i * 4 + 2];
        v.w = 0.5f * feats[i * 4 + 3];
        d_x0[i] = v;
        d_y[i]  = v;
    }
}

// ---------------- propagation: one warp per dst node ----------------
__global__ void propagate_kernel(int dir) {
    const float4* __restrict__ xin  = dir ? d_x1 : d_x0;
    float4* __restrict__       xout = dir ? d_x0 : d_x1;

    int warp = (blockIdx.x * blockDim.x + threadIdx.x) >> 5;
    int lane = threadIdx.x & 31;
    if (warp >= NN) return;

    int beg = d_rowptr[warp];
    int end = d_rowptr[warp + 1];
    float4 acc = make_float4(0.f, 0.f, 0.f, 0.f);
    for (int e = beg; e < end; e++) {
        int   s  = d_col[e];
        float ww = d_w[e];
        float4 v = xin[s * 32 + lane];
        acc.x += ww * v.x;
        acc.y += ww * v.y;
        acc.z += ww * v.z;
        acc.w += ww * v.w;
    }
    int o = warp * 32 + lane;
    xout[o] = acc;
    float4 yv = d_y[o];
    yv.x += acc.x; yv.y += acc.y; yv.z += acc.z; yv.w += acc.w;
    d_y[o] = yv;
}

// ---------------- fused (y/5) @ W1 -> relu -> @ W2 ----------------
// smem layout (floats): sW1[128*128] | sW2[128*64] | sY[64*132] | sH[64*132]
#define SY_STRIDE 132
#define GEMM_SMEM ((16384 + 8192 + 64 * SY_STRIDE + 64 * SY_STRIDE) * 4)

__global__ void gemm_fused_kernel(const float* __restrict__ W1,
                                  const float* __restrict__ W2,
                                  float* __restrict__ out) {
    extern __shared__ float sm[];
    float* sW1 = sm;                       // [128][128]
    float* sW2 = sm + 16384;               // [128][64]
    float* sY  = sm + 16384 + 8192;        // [64][132]
    float* sH  = sY + 64 * SY_STRIDE;      // [64][132]

    int t = threadIdx.x;            // 256 threads
    int rowBase = blockIdx.x * 64;

    // load W1 (4096 float4)
    {
        const float4* W14 = (const float4*)W1;
        float4* s4 = (float4*)sW1;
        #pragma unroll
        for (int i = 0; i < 16; i++) s4[i * 256 + t] = W14[i * 256 + t];
    }
    // load W2 (2048 float4)
    {
        const float4* W24 = (const float4*)W2;
        float4* s4 = (float4*)sW2;
        #pragma unroll
        for (int i = 0; i < 8; i++) s4[i * 256 + t] = W24[i * 256 + t];
    }
    // load Y tile, scaled by 1/(K+1) = 0.2
    {
        #pragma unroll
        for (int i = 0; i < 8; i++) {
            int idx = i * 256 + t;           // 0..2047
            int r   = idx >> 5;
            int c4  = idx & 31;
            int gr  = rowBase + r;
            float4 v = make_float4(0.f, 0.f, 0.f, 0.f);
            if (gr < NN) v = d_y[gr * 32 + c4];
            v.x *= 0.2f; v.y *= 0.2f; v.z *= 0.2f; v.w *= 0.2f;
            *(float4*)&sY[r * SY_STRIDE + c4 * 4] = v;
        }
    }
    __syncthreads();

    int tx = t & 15;    // 16 col groups
    int ty = t >> 4;    // 16 row groups

    // phase A: H[64][128] = relu(Y @ W1), thread tile 4 rows x 8 cols
    {
        float acc[4][8];
        #pragma unroll
        for (int i = 0; i < 4; i++)
            #pragma unroll
            for (int j = 0; j < 8; j++) acc[i][j] = 0.f;

        #pragma unroll 4
        for (int k = 0; k < 128; k++) {
            float4 b0 = *(const float4*)&sW1[k * 128 + tx * 8];
            float4 b1 = *(const float4*)&sW1[k * 128 + tx * 8 + 4];
            float a0 = sY[(ty * 4 + 0) * SY_STRIDE + k];
            float a1 = sY[(ty * 4 + 1) * SY_STRIDE + k];
            float a2 = sY[(ty * 4 + 2) * SY_STRIDE + k];
            float a3 = sY[(ty * 4 + 3) * SY_STRIDE + k];
            float bb[8] = {b0.x, b0.y, b0.z, b0.w, b1.x, b1.y, b1.z, b1.w};
            #pragma unroll
            for (int j = 0; j < 8; j++) {
                acc[0][j] += a0 * bb[j];
                acc[1][j] += a1 * bb[j];
                acc[2][j] += a2 * bb[j];
                acc[3][j] += a3 * bb[j];
            }
        }
        #pragma unroll
        for (int i = 0; i < 4; i++)
            #pragma unroll
            for (int j = 0; j < 8; j++)
                sH[(ty * 4 + i) * SY_STRIDE + tx * 8 + j] = fmaxf(acc[i][j], 0.f);
    }
    __syncthreads();

    // phase B: out[64][64] = H @ W2, thread tile 4 rows x 4 cols
    {
        float acc[4][4];
        #pragma unroll
        for (int i = 0; i < 4; i++)
            #pragma unroll
            for (int j = 0; j < 4; j++) acc[i][j] = 0.f;

        #pragma unroll 4
        for (int k = 0; k < 128; k++) {
            float4 b = *(const float4*)&sW2[k * 64 + tx * 4];
            float a0 = sH[(ty * 4 + 0) * SY_STRIDE + k];
            float a1 = sH[(ty * 4 + 1) * SY_STRIDE + k];
            float a2 = sH[(ty * 4 + 2) * SY_STRIDE + k];
            float a3 = sH[(ty * 4 + 3) * SY_STRIDE + k];
            float bb[4] = {b.x, b.y, b.z, b.w};
            #pragma unroll
            for (int j = 0; j < 4; j++) {
                acc[0][j] += a0 * bb[j];
                acc[1][j] += a1 * bb[j];
                acc[2][j] += a2 * bb[j];
                acc[3][j] += a3 * bb[j];
            }
        }
        #pragma unroll
        for (int i = 0; i < 4; i++) {
            int gr = rowBase + ty * 4 + i;
            if (gr < NN) {
                float4 v = make_float4(acc[i][0], acc[i][1], acc[i][2], acc[i][3]);
                ((float4*)out)[gr * 16 + tx] = v;
            }
        }
    }
}

// ---------------- launch ----------------
extern "C" void kernel_launch(void* const* d_in, const int* in_sizes, int n_in,
                              void* d_out, int out_size) {
    const float* feats = (const float*)d_in[0];
    const float* W1    = (const float*)d_in[1];
    const float* W2    = (const float*)d_in[2];
    const int*   ei32  = (const int*)d_in[3];
    float*       out   = (float*)d_out;

    cudaFuncSetAttribute(gemm_fused_kernel,
                         cudaFuncAttributeMaxDynamicSharedMemorySize, GEMM_SMEM);

    // detect edge dtype (int32 vs int64), deterministic each call
    detect_kernel<<<1, 32>>>(ei32);

    // CSR build
    zero_deg_kernel<<<(NN + 255) / 256, 256>>>();
    hist_kernel<<<(NE + 255) / 256, 256>>>(ei32);
    norm_kernel<<<(NN + 255) / 256, 256>>>();
    scan1_kernel<<<SCAN_B, 1024>>>();
    scan2_kernel<<<1, 32>>>();
    scan3_kernel<<<(NN + 255) / 256, 256>>>();
    fill_kernel<<<(NE + 255) / 256, 256>>>(ei32);

    // init x0 = feats*0.5, y = x0
    init_kernel<<<(NN * 32 + 255) / 256, 256>>>(feats);

    // 4 propagation rounds (ping-pong x0/x1, accumulate into y)
    int prop_grid = (NN * 32 + 255) / 256;   // one warp per node
    propagate_kernel<<<prop_grid, 256>>>(0);
    propagate_kernel<<<prop_grid, 256>>>(1);
    propagate_kernel<<<prop_grid, 256>>>(0);
    propagate_kernel<<<prop_grid, 256>>>(1);

    // fused MLP
    gemm_fused_kernel<<<(NN + 63) / 64, 256, GEMM_SMEM>>>(W1, W2, out);
}

// round 3
// speedup vs baseline: 1.0924x; 1.0924x over previous
#include <cuda_runtime.h>
#include <cuda_fp16.h>
#include <math.h>

#define NN 100000
#define NE 1600000
#define D 128
#define DOUT 64

// ---------------- scratch (static device globals; no allocs) ----------------
// 5 propagation states x0..x4 in fp16: [5][NN nodes][32 x uint2(=4 half)] = 128 MB
__device__ uint2 d_hx[5][NN * 32];
__device__ uint2 d_edge[NE];          // {src, w(fp32 bits)} packed, 12.8 MB
__device__ int   d_deg[NN];
__device__ float d_norm[NN];
__device__ int   d_rowptr[NN + 1];
__device__ int   d_cursor[NN];
__device__ int   d_bsums[128];
__device__ int   d_is64;

#define SCAN_B 98   // ceil(100000/1024)

// ---------------- edge dtype detect ----------------
// int64 positive values < 2^31 have zero high words at odd int32 indices.
__global__ void detect_kernel(const int* __restrict__ ei32) {
    if (threadIdx.x == 0) {
        int all_zero = 1;
        #pragma unroll
        for (int i = 0; i < 32; i++)
            if (ei32[2 * i + 1] != 0) all_zero = 0;
        d_is64 = all_zero;
    }
}

__device__ __forceinline__ int load_edge(const int* ei32, int row, int e) {
    int v;
    if (d_is64) v = ei32[2 * (row * NE + e)];     // int64 layout, low word
    else        v = ei32[row * NE + e];           // int32 layout
    return (v < 0) ? 0 : (v >= NN ? NN - 1 : v);  // clamp: never fault
}

// ---------------- CSR build ----------------
__global__ void zero_deg_kernel() {
    int i = blockIdx.x * blockDim.x + threadIdx.x;
    if (i < NN) d_deg[i] = 0;
}

__global__ void hist_kernel(const int* __restrict__ ei32) {
    int e = blockIdx.x * blockDim.x + threadIdx.x;
    if (e < NE) {
        int dst = load_edge(ei32, 1, e);
        atomicAdd(&d_deg[dst], 1);
    }
}

__global__ void norm_kernel() {
    int i = blockIdx.x * blockDim.x + threadIdx.x;
    if (i < NN) {
        float dg = (float)d_deg[i];
        d_norm[i] = rsqrtf(fmaxf(dg, 1.0f));
    }
}

__global__ void scan1_kernel() {
    __shared__ int s[1024];
    int tid = threadIdx.x;
    int idx = blockIdx.x * 1024 + tid;
    int c = (idx < NN) ? d_deg[idx] : 0;
    s[tid] = c;
    __syncthreads();
    #pragma unroll
    for (int off = 1; off < 1024; off <<= 1) {
        int v = (tid >= off) ? s[tid - off] : 0;
        __syncthreads();
        s[tid] += v;
        __syncthreads();
    }
    if (idx < NN) d_rowptr[idx] = s[tid] - c;   // exclusive within block
    if (tid == 1023) d_bsums[blockIdx.x] = s[1023];
}

__global__ void scan2_kernel() {
    if (threadIdx.x == 0 && blockIdx.x == 0) {
        int run = 0;
        for (int i = 0; i < SCAN_B; i++) {
            int t = d_bsums[i];
            d_bsums[i] = run;
            run += t;
        }
    }
}

__global__ void scan3_kernel() {
    int i = blockIdx.x * blockDim.x + threadIdx.x;
    if (i < NN) {
        int r = d_rowptr[i] + d_bsums[i >> 10];
        d_rowptr[i] = r;
        d_cursor[i] = r;
    }
    if (i == 0) d_rowptr[NN] = NE;
}

__global__ void fill_kernel(const int* __restrict__ ei32) {
    int e = blockIdx.x * blockDim.x + threadIdx.x;
    if (e < NE) {
        int src = load_edge(ei32, 0, e);
        int dst = load_edge(ei32, 1, e);
        int pos = atomicAdd(&d_cursor[dst], 1);
        if (pos < NE) {
            uint2 ev;
            ev.x = (unsigned)src;
            ev.y = __float_as_uint(d_norm[src] * d_norm[dst]);
            d_edge[pos] = ev;
        }
    }
}

// ---------------- init: x0 = fp16(feats)  (scales folded into GEMM) ----------
__global__ void init_kernel(const float* __restrict__ feats) {
    int i = blockIdx.x * blockDim.x + threadIdx.x;   // uint2 index, NN*32 total
    if (i < NN * 32) {
        float4 v = ((const float4*)feats)[i];
        __half2 p0 = __floats2half2_rn(v.x, v.y);
        __half2 p1 = __floats2half2_rn(v.z, v.w);
        uint2 o;
        o.x = *(unsigned*)&p0;
        o.y = *(unsigned*)&p1;
        d_hx[0][i] = o;
    }
}

// ---------------- propagation: one warp per dst node, fp16 gather ------------
__global__ void propagate_kernel(int k) {
    const uint2* __restrict__ xin  = d_hx[k - 1];
    uint2* __restrict__       xout = d_hx[k];

    int warp = (blockIdx.x * blockDim.x + threadIdx.x) >> 5;
    int lane = threadIdx.x & 31;
    if (warp >= NN) return;

    int beg = d_rowptr[warp];
    int end = d_rowptr[warp + 1];
    float a0 = 0.f, a1 = 0.f, a2 = 0.f, a3 = 0.f;
    for (int e = beg; e < end; e++) {
        uint2 ee = d_edge[e];                 // broadcast across warp
        int   s  = (int)ee.x;
        float ww = __uint_as_float(ee.y);
        uint2 v = xin[s * 32 + lane];
        float2 f0 = __half22float2(*(__half2*)&v.x);
        float2 f1 = __half22float2(*(__half2*)&v.y);
        a0 += ww * f0.x;
        a1 += ww * f0.y;
        a2 += ww * f1.x;
        a3 += ww * f1.y;
    }
    __half2 p0 = __floats2half2_rn(a0, a1);
    __half2 p1 = __floats2half2_rn(a2, a3);
    uint2 o;
    o.x = *(unsigned*)&p0;
    o.y = *(unsigned*)&p1;
    xout[warp * 32 + lane] = o;
}

// ---------------- fused 0.1*(sum x_i) @ W1 -> relu -> @ W2 -------------------
// smem layout (floats): sW1[128*128] | sW2[128*64] | sY[64*132] | sH[64*132]
#define SY_STRIDE 132
#define GEMM_SMEM ((16384 + 8192 + 64 * SY_STRIDE + 64 * SY_STRIDE) * 4)

__global__ void gemm_fused_kernel(const float* __restrict__ W1,
                                  const float* __restrict__ W2,
                                  float* __restrict__ out) {
    extern __shared__ float sm[];
    float* sW1 = sm;                       // [128][128]
    float* sW2 = sm + 16384;               // [128][64]
    float* sY  = sm + 16384 + 8192;        // [64][132]
    float* sH  = sY + 64 * SY_STRIDE;      // [64][132]

    int t = threadIdx.x;            // 256 threads
    int rowBase = blockIdx.x * 64;

    // load W1 (4096 float4)
    {
        const float4* W14 = (const float4*)W1;
        float4* s4 = (float4*)sW1;
        #pragma unroll
        for (int i = 0; i < 16; i++) s4[i * 256 + t] = W14[i * 256 + t];
    }
    // load W2 (2048 float4)
    {
        const float4* W24 = (const float4*)W2;
        float4* s4 = (float4*)sW2;
        #pragma unroll
        for (int i = 0; i < 8; i++) s4[i * 256 + t] = W24[i * 256 + t];
    }
    // build Y tile = 0.1 * sum_{b=0..4} x_b   (0.5 drop-node * 0.2 order scale)
    {
        #pragma unroll
        for (int i = 0; i < 8; i++) {
            int idx = i * 256 + t;           // 0..2047 (64 rows x 32 uint2)
            int r   = idx >> 5;
            int c   = idx & 31;
            int gr  = rowBase + r;
            float s0 = 0.f, s1 = 0.f, s2 = 0.f, s3 = 0.f;
            if (gr < NN) {
                #pragma unroll
                for (int b = 0; b < 5; b++) {
                    uint2 v = d_hx[b][gr * 32 + c];
                    float2 f0 = __half22float2(*(__half2*)&v.x);
                    float2 f1 = __half22float2(*(__half2*)&v.y);
                    s0 += f0.x; s1 += f0.y; s2 += f1.x; s3 += f1.y;
                }
            }
            float4 v4 = make_float4(0.1f * s0, 0.1f * s1, 0.1f * s2, 0.1f * s3);
            *(float4*)&sY[r * SY_STRIDE + c * 4] = v4;
        }
    }
    __syncthreads();

    int tx = t & 15;    // 16 col groups
    int ty = t >> 4;    // 16 row groups

    // phase A: H[64][128] = relu(Y @ W1), thread tile 4 rows x 8 cols
    {
        float acc[4][8];
        #pragma unroll
        for (int i = 0; i < 4; i++)
            #pragma unroll
            for (int j = 0; j < 8; j++) acc[i][j] = 0.f;

        #pragma unroll 4
        for (int k = 0; k < 128; k++) {
            float4 b0 = *(const float4*)&sW1[k * 128 + tx * 8];
            float4 b1 = *(const float4*)&sW1[k * 128 + tx * 8 + 4];
            float v0 = sY[(ty * 4 + 0) * SY_STRIDE + k];
            float v1 = sY[(ty * 4 + 1) * SY_STRIDE + k];
            float v2 = sY[(ty * 4 + 2) * SY_STRIDE + k];
            float v3 = sY[(ty * 4 + 3) * SY_STRIDE + k];
            float bb[8] = {b0.x, b0.y, b0.z, b0.w, b1.x, b1.y, b1.z, b1.w};
            #pragma unroll
            for (int j = 0; j < 8; j++) {
                acc[0][j] += v0 * bb[j];
                acc[1][j] += v1 * bb[j];
                acc[2][j] += v2 * bb[j];
                acc[3][j] += v3 * bb[j];
            }
        }
        #pragma unroll
        for (int i = 0; i < 4; i++)
            #pragma unroll
            for (int j = 0; j < 8; j++)
                sH[(ty * 4 + i) * SY_STRIDE + tx * 8 + j] = fmaxf(acc[i][j], 0.f);
    }
    __syncthreads();

    // phase B: out[64][64] = H @ W2, thread tile 4 rows x 4 cols
    {
        float acc[4][4];
        #pragma unroll
        for (int i = 0; i < 4; i++)
            #pragma unroll
            for (int j = 0; j < 4; j++) acc[i][j] = 0.f;

        #pragma unroll 4
        for (int k = 0; k < 128; k++) {
            float4 b = *(const float4*)&sW2[k * 64 + tx * 4];
            float v0 = sH[(ty * 4 + 0) * SY_STRIDE + k];
            float v1 = sH[(ty * 4 + 1) * SY_STRIDE + k];
            float v2 = sH[(ty * 4 + 2) * SY_STRIDE + k];
            float v3 = sH[(ty * 4 + 3) * SY_STRIDE + k];
            float bb[4] = {b.x, b.y, b.z, b.w};
            #pragma unroll
            for (int j = 0; j < 4; j++) {
                acc[0][j] += v0 * bb[j];
                acc[1][j] += v1 * bb[j];
                acc[2][j] += v2 * bb[j];
                acc[3][j] += v3 * bb[j];
            }
        }
        #pragma unroll
        for (int i = 0; i < 4; i++) {
            int gr = rowBase + ty * 4 + i;
            if (gr < NN) {
                float4 v = make_float4(acc[i][0], acc[i][1], acc[i][2], acc[i][3]);
                ((float4*)out)[gr * 16 + tx] = v;
            }
        }
    }
}

// ---------------- launch ----------------
extern "C" void kernel_launch(void* const* d_in, const int* in_sizes, int n_in,
                              void* d_out, int out_size) {
    const float* feats = (const float*)d_in[0];
    const float* W1    = (const float*)d_in[1];
    const float* W2    = (const float*)d_in[2];
    const int*   ei32  = (const int*)d_in[3];
    float*       out   = (float*)d_out;

    cudaFuncSetAttribute(gemm_fused_kernel,
                         cudaFuncAttributeMaxDynamicSharedMemorySize, GEMM_SMEM);

    // detect edge dtype (int32 vs int64), deterministic each call
    detect_kernel<<<1, 32>>>(ei32);

    // CSR build
    zero_deg_kernel<<<(NN + 255) / 256, 256>>>();
    hist_kernel<<<(NE + 255) / 256, 256>>>(ei32);
    norm_kernel<<<(NN + 255) / 256, 256>>>();
    scan1_kernel<<<SCAN_B, 1024>>>();
    scan2_kernel<<<1, 32>>>();
    scan3_kernel<<<(NN + 255) / 256, 256>>>();
    fill_kernel<<<(NE + 255) / 256, 256>>>(ei32);

    // init x0 = fp16(feats)
    init_kernel<<<(NN * 32 + 255) / 256, 256>>>(feats);

    // 4 propagation rounds x0 -> x1 -> x2 -> x3 -> x4
    int prop_grid = (NN * 32 + 255) / 256;   // one warp per node
    propagate_kernel<<<prop_grid, 256>>>(1);
    propagate_kernel<<<prop_grid, 256>>>(2);
    propagate_kernel<<<prop_grid, 256>>>(3);
    propagate_kernel<<<prop_grid, 256>>>(4);

    // fused MLP over 0.1 * sum(x_i)
    gemm_fused_kernel<<<(NN + 63) / 64, 256, GEMM_SMEM>>>(W1, W2, out);
}

// round 4
// speedup vs baseline: 1.6323x; 1.4943x over previous
#include <cuda_runtime.h>
#include <cuda_fp16.h>
#include <math.h>

#define NN 100000
#define NE 1600000
#define D 128
#define DOUT 64

// ---------------- scratch (static device globals; no allocs) ----------------
__device__ uint2  d_hx[5][NN * 32];   // x0..x4 fp16, 128 MB
__device__ uint2  d_edge[NE];         // {src, w} packed
__device__ __half d_W1h[D * D];
__device__ __half d_W2h[D * DOUT];
__device__ int    d_deg[NN];
__device__ float  d_norm[NN];
__device__ int    d_rowptr[NN + 1];
__device__ int    d_cursor[NN];
__device__ int    d_bsums[128];
__device__ int    d_is64;

#define SCAN_B 98

// ---------------- edge dtype detect ----------------
__global__ void detect_kernel(const int* __restrict__ ei32) {
    if (threadIdx.x == 0) {
        int all_zero = 1;
        #pragma unroll
        for (int i = 0; i < 32; i++)
            if (ei32[2 * i + 1] != 0) all_zero = 0;
        d_is64 = all_zero;
    }
}

__device__ __forceinline__ int load_edge(const int* ei32, int row, int e) {
    int v;
    if (d_is64) v = ei32[2 * (row * NE + e)];
    else        v = ei32[row * NE + e];
    return (v < 0) ? 0 : (v >= NN ? NN - 1 : v);
}

// ---------------- CSR build ----------------
__global__ void zero_deg_kernel() {
    int i = blockIdx.x * blockDim.x + threadIdx.x;
    if (i < NN) d_deg[i] = 0;
}

__global__ void hist_kernel(const int* __restrict__ ei32) {
    int e = blockIdx.x * blockDim.x + threadIdx.x;
    if (e < NE) atomicAdd(&d_deg[load_edge(ei32, 1, e)], 1);
}

__global__ void norm_kernel() {
    int i = blockIdx.x * blockDim.x + threadIdx.x;
    if (i < NN) d_norm[i] = rsqrtf(fmaxf((float)d_deg[i], 1.0f));
}

__global__ void scan1_kernel() {
    __shared__ int s[1024];
    int tid = threadIdx.x;
    int idx = blockIdx.x * 1024 + tid;
    int c = (idx < NN) ? d_deg[idx] : 0;
    s[tid] = c;
    __syncthreads();
    #pragma unroll
    for (int off = 1; off < 1024; off <<= 1) {
        int v = (tid >= off) ? s[tid - off] : 0;
        __syncthreads();
        s[tid] += v;
        __syncthreads();
    }
    if (idx < NN) d_rowptr[idx] = s[tid] - c;
    if (tid == 1023) d_bsums[blockIdx.x] = s[1023];
}

__global__ void scan2_kernel() {
    if (threadIdx.x == 0 && blockIdx.x == 0) {
        int run = 0;
        for (int i = 0; i < SCAN_B; i++) { int t = d_bsums[i]; d_bsums[i] = run; run += t; }
    }
}

__global__ void scan3_kernel() {
    int i = blockIdx.x * blockDim.x + threadIdx.x;
    if (i < NN) {
        int r = d_rowptr[i] + d_bsums[i >> 10];
        d_rowptr[i] = r;
        d_cursor[i] = r;
    }
    if (i == 0) d_rowptr[NN] = NE;
}

__global__ void fill_kernel(const int* __restrict__ ei32) {
    int e = blockIdx.x * blockDim.x + threadIdx.x;
    if (e < NE) {
        int src = load_edge(ei32, 0, e);
        int dst = load_edge(ei32, 1, e);
        int pos = atomicAdd(&d_cursor[dst], 1);
        if (pos < NE) {
            uint2 ev;
            ev.x = (unsigned)src;
            ev.y = __float_as_uint(d_norm[src] * d_norm[dst]);
            d_edge[pos] = ev;
        }
    }
}

// ---------------- init x0 = fp16(feats); convert weights -------------------
__global__ void init_kernel(const float* __restrict__ feats) {
    int i = blockIdx.x * blockDim.x + threadIdx.x;
    if (i < NN * 32) {
        float4 v = ((const float4*)feats)[i];
        __half2 p0 = __floats2half2_rn(v.x, v.y);
        __half2 p1 = __floats2half2_rn(v.z, v.w);
        uint2 o;
        o.x = *(unsigned*)&p0;
        o.y = *(unsigned*)&p1;
        d_hx[0][i] = o;
    }
}

__global__ void prep_w_kernel(const float* __restrict__ W1, const float* __restrict__ W2) {
    int i = blockIdx.x * blockDim.x + threadIdx.x;
    if (i < D * D) d_W1h[i] = __float2half(W1[i]);
    if (i < D * DOUT) d_W2h[i] = __float2half(W2[i]);
}

// ---------------- propagation: warp per node, 4-deep pipelined -------------
__global__ void propagate_kernel(int k) {
    const uint2* __restrict__ xin  = d_hx[k - 1];
    uint2* __restrict__       xout = d_hx[k];

    int warp = (blockIdx.x * blockDim.x + threadIdx.x) >> 5;
    int lane = threadIdx.x & 31;
    if (warp >= NN) return;

    int beg = d_rowptr[warp];
    int end = d_rowptr[warp + 1];
    float a0 = 0.f, a1 = 0.f, a2 = 0.f, a3 = 0.f;

    int e = beg;
    for (; e + 4 <= end; e += 4) {
        uint2 e0 = d_edge[e], e1 = d_edge[e + 1], e2 = d_edge[e + 2], e3 = d_edge[e + 3];
        uint2 v0 = xin[(int)e0.x * 32 + lane];
        uint2 v1 = xin[(int)e1.x * 32 + lane];
        uint2 v2 = xin[(int)e2.x * 32 + lane];
        uint2 v3 = xin[(int)e3.x * 32 + lane];
        float w0 = __uint_as_float(e0.y), w1 = __uint_as_float(e1.y);
        float w2 = __uint_as_float(e2.y), w3 = __uint_as_float(e3.y);
        float2 f;
        f = __half22float2(*(__half2*)&v0.x); a0 += w0 * f.x; a1 += w0 * f.y;
        f = __half22float2(*(__half2*)&v0.y); a2 += w0 * f.x; a3 += w0 * f.y;
        f = __half22float2(*(__half2*)&v1.x); a0 += w1 * f.x; a1 += w1 * f.y;
        f = __half22float2(*(__half2*)&v1.y); a2 += w1 * f.x; a3 += w1 * f.y;
        f = __half22float2(*(__half2*)&v2.x); a0 += w2 * f.x; a1 += w2 * f.y;
        f = __half22float2(*(__half2*)&v2.y); a2 += w2 * f.x; a3 += w2 * f.y;
        f = __half22float2(*(__half2*)&v3.x); a0 += w3 * f.x; a1 += w3 * f.y;
        f = __half22float2(*(__half2*)&v3.y); a2 += w3 * f.x; a3 += w3 * f.y;
    }
    for (; e < end; e++) {
        uint2 ee = d_edge[e];
        float ww = __uint_as_float(ee.y);
        uint2 v = xin[(int)ee.x * 32 + lane];
        float2 f0 = __half22float2(*(__half2*)&v.x);
        float2 f1 = __half22float2(*(__half2*)&v.y);
        a0 += ww * f0.x; a1 += ww * f0.y; a2 += ww * f1.x; a3 += ww * f1.y;
    }
    __half2 p0 = __floats2half2_rn(a0, a1);
    __half2 p1 = __floats2half2_rn(a2, a3);
    uint2 o;
    o.x = *(unsigned*)&p0;
    o.y = *(unsigned*)&p1;
    xout[warp * 32 + lane] = o;
}

// ---------------- tensor-core fused MLP ------------------------------------
// out = relu(0.1*sum(x_i) @ W1) @ W2, via mma.sync m16n8k16 fp16->fp32
#define YST  136
#define W1ST 136
#define W2ST 72
#define HST  136
// halves: W1 17408 | W2 9216 | Y 8704 | H 8704 = 44032 halves = 88064 B
#define OFF_W1 0
#define OFF_W2 17408
#define OFF_Y  26624
#define OFF_H  35328
#define GEMM_SMEM (44032 * 2)

__device__ __forceinline__ void ldsm_x4(unsigned addr, unsigned& r0, unsigned& r1,
                                        unsigned& r2, unsigned& r3) {
    asm volatile("ldmatrix.sync.aligned.m8n8.x4.shared.b16 {%0,%1,%2,%3}, [%4];"
                 : "=r"(r0), "=r"(r1), "=r"(r2), "=r"(r3) : "r"(addr));
}
__device__ __forceinline__ void ldsm_x2t(unsigned addr, unsigned& r0, unsigned& r1) {
    asm volatile("ldmatrix.sync.aligned.m8n8.x2.trans.shared.b16 {%0,%1}, [%2];"
                 : "=r"(r0), "=r"(r1) : "r"(addr));
}
__device__ __forceinline__ void mma_16816(float& d0, float& d1, float& d2, float& d3,
                                          unsigned a0, unsigned a1, unsigned a2, unsigned a3,
                                          unsigned b0, unsigned b1) {
    asm volatile("mma.sync.aligned.m16n8k16.row.col.f32.f16.f16.f32 "
                 "{%0,%1,%2,%3}, {%4,%5,%6,%7}, {%8,%9}, {%0,%1,%2,%3};"
                 : "+f"(d0), "+f"(d1), "+f"(d2), "+f"(d3)
                 : "r"(a0), "r"(a1), "r"(a2), "r"(a3), "r"(b0), "r"(b1));
}

__global__ void gemm_fused_kernel(float* __restrict__ out) {
    extern __shared__ __half sh[];
    unsigned sbase = (unsigned)__cvta_generic_to_shared(sh);

    int t = threadIdx.x;        // 128 threads, 4 warps
    int lane = t & 31;
    int w = t >> 5;
    int rowBase = blockIdx.x * 64;

    // ---- load W1h -> smem (2048 uint4) ----
    {
        const uint4* g = (const uint4*)d_W1h;
        #pragma unroll
        for (int i = 0; i < 16; i++) {
            int idx = i * 128 + t;          // 0..2047
            int r = idx >> 4, c4 = idx & 15;
            *(uint4*)&sh[OFF_W1 + r * W1ST + c4 * 8] = g[idx];
        }
    }
    // ---- load W2h -> smem (1024 uint4) ----
    {
        const uint4* g = (const uint4*)d_W2h;
        #pragma unroll
        for (int i = 0; i < 8; i++) {
            int idx = i * 128 + t;          // 0..1023
            int r = idx >> 3, c4 = idx & 7;
            *(uint4*)&sh[OFF_W2 + r * W2ST + c4 * 8] = g[idx];
        }
    }
    // ---- build Y tile = fp16(0.1 * sum_b x_b) ----
    {
        #pragma unroll
        for (int i = 0; i < 16; i++) {
            int idx = i * 128 + t;          // 0..2047 : 64 rows x 32 uint2 cols
            int r = idx >> 5, c = idx & 31;
            int gr = rowBase + r;
            float s0 = 0.f, s1 = 0.f, s2 = 0.f, s3 = 0.f;
            if (gr < NN) {
                #pragma unroll
                for (int b = 0; b < 5; b++) {
                    uint2 v = d_hx[b][gr * 32 + c];
                    float2 f0 = __half22float2(*(__half2*)&v.x);
                    float2 f1 = __half22float2(*(__half2*)&v.y);
                    s0 += f0.x; s1 += f0.y; s2 += f1.x; s3 += f1.y;
                }
            }
            __half2 p0 = __floats2half2_rn(0.1f * s0, 0.1f * s1);
            __half2 p1 = __floats2half2_rn(0.1f * s2, 0.1f * s3);
            uint2 o;
            o.x = *(unsigned*)&p0;
            o.y = *(unsigned*)&p1;
            *(uint2*)&sh[OFF_Y + r * YST + c * 4] = o;
        }
    }
    __syncthreads();

    // A-frag lane addressing (shared by both phases)
    int g_  = lane >> 3;
    int ar  = (g_ & 1) * 8 + (lane & 7);   // row within 16
    int ac  = (g_ >> 1) * 8;               // col offset within 16
    int bk  = lane & 15;                    // B k-row within 16

    // ---- phase A: H = relu(Y @ W1) ----
    {
        unsigned aF[8][4];
        #pragma unroll
        for (int ks = 0; ks < 8; ks++) {
            unsigned addr = sbase + (OFF_Y + (w * 16 + ar) * YST + ks * 16 + ac) * 2;
            ldsm_x4(addr, aF[ks][0], aF[ks][1], aF[ks][2], aF[ks][3]);
        }
        #pragma unroll
        for (int nt = 0; nt < 16; nt++) {
            float d0 = 0.f, d1 = 0.f, d2 = 0.f, d3 = 0.f;
            #pragma unroll
            for (int ks = 0; ks < 8; ks++) {
                unsigned b0, b1;
                unsigned baddr = sbase + (OFF_W1 + (ks * 16 + bk) * W1ST + nt * 8) * 2;
                ldsm_x2t(baddr, b0, b1);
                mma_16816(d0, d1, d2, d3, aF[ks][0], aF[ks][1], aF[ks][2], aF[ks][3], b0, b1);
            }
            // relu + store fp16 to sH
            int hr = w * 16 + (lane >> 2);
            int hc = nt * 8 + (lane & 3) * 2;
            __half2 h01 = __floats2half2_rn(fmaxf(d0, 0.f), fmaxf(d1, 0.f));
            __half2 h23 = __floats2half2_rn(fmaxf(d2, 0.f), fmaxf(d3, 0.f));
            *(unsigned*)&sh[OFF_H + hr * HST + hc]       = *(unsigned*)&h01;
            *(unsigned*)&sh[OFF_H + (hr + 8) * HST + hc] = *(unsigned*)&h23;
        }
    }
    __syncthreads();

    // ---- phase B: out = H @ W2 ----
    {
        unsigned hF[8][4];
        #pragma unroll
        for (int ks = 0; ks < 8; ks++) {
            unsigned addr = sbase + (OFF_H + (w * 16 + ar) * HST + ks * 16 + ac) * 2;
            ldsm_x4(addr, hF[ks][0], hF[ks][1], hF[ks][2], hF[ks][3]);
        }
        #pragma unroll
        for (int nt = 0; nt < 8; nt++) {
            float d0 = 0.f, d1 = 0.f, d2 = 0.f, d3 = 0.f;
            #pragma unroll
            for (int ks = 0; ks < 8; ks++) {
                unsigned b0, b1;
                unsigned baddr = sbase + (OFF_W2 + (ks * 16 + bk) * W2ST + nt * 8) * 2;
                ldsm_x2t(baddr, b0, b1);
                mma_16816(d0, d1, d2, d3, hF[ks][0], hF[ks][1], hF[ks][2], hF[ks][3], b0, b1);
            }
            int row = w * 16 + (lane >> 2);
            int c   = nt * 8 + (lane & 3) * 2;
            int gr0 = rowBase + row;
            int gr1 = gr0 + 8;
            if (gr0 < NN) *(float2*)&out[gr0 * DOUT + c] = make_float2(d0, d1);
            if (gr1 < NN) *(float2*)&out[gr1 * DOUT + c] = make_float2(d2, d3);
        }
    }
}

// ---------------- launch ----------------
extern "C" void kernel_launch(void* const* d_in, const int* in_sizes, int n_in,
                              void* d_out, int out_size) {
    const float* feats = (const float*)d_in[0];
    const float* W1    = (const float*)d_in[1];
    const float* W2    = (const float*)d_in[2];
    const int*   ei32  = (const int*)d_in[3];
    float*       out   = (float*)d_out;

    cudaFuncSetAttribute(gemm_fused_kernel,
                         cudaFuncAttributeMaxDynamicSharedMemorySize, GEMM_SMEM);

    detect_kernel<<<1, 32>>>(ei32);

    zero_deg_kernel<<<(NN + 255) / 256, 256>>>();
    hist_kernel<<<(NE + 255) / 256, 256>>>(ei32);
    norm_kernel<<<(NN + 255) / 256, 256>>>();
    scan1_kernel<<<SCAN_B, 1024>>>();
    scan2_kernel<<<1, 32>>>();
    scan3_kernel<<<(NN + 255) / 256, 256>>>();
    fill_kernel<<<(NE + 255) / 256, 256>>>(ei32);

    init_kernel<<<(NN * 32 + 255) / 256, 256>>>(feats);
    prep_w_kernel<<<(D * D + 255) / 256, 256>>>(W1, W2);

    int prop_grid = (NN * 32 + 255) / 256;
    propagate_kernel<<<prop_grid, 256>>>(1);
    propagate_kernel<<<prop_grid, 256>>>(2);
    propagate_kernel<<<prop_grid, 256>>>(3);
    propagate_kernel<<<prop_grid, 256>>>(4);

    gemm_fused_kernel<<<(NN + 63) / 64, 128, GEMM_SMEM>>>(out);
}